// round 9
// baseline (speedup 1.0000x reference)
#include <cuda_runtime.h>
#include <cstdint>

// Problem constants
#define AN 3
#define SSZ 32
#define HH 128
#define WW 128
#define KK (SSZ*HH*WW)        // 524288 spatial positions
#define NN (KK*AN)            // 1572864 total anchors
#define PRE 2000
#define POST 300
#define WORDS 32              // 2048 bits >= PRE
#define MSUB 128              // 16-column chunks per row (WORDS*4)
#define CAP 4096
#define NMS_T 0.7f
#define TC 0.99834f           // static stash threshold (fast path)

typedef unsigned long long u64;

// ---------------- device state ----------------
__device__ unsigned int g_hist1[65536];
__device__ unsigned int g_hist2[65536];
__device__ int          g_cand_count;      // zero-init; reset by final_k
__device__ u64          g_cand[CAP];

__device__ int   g_order[PRE];
__device__ float g_score[PRE];
__device__ float g_bx1[PRE], g_by1[PRE], g_bz1[PRE];
__device__ float g_bx2[PRE], g_by2[PRE], g_bz2[PRE];
__device__ float g_volv[PRE];
__device__ int   g_valid[PRE];
__device__ u64   g_mask[PRE*WORDS];        // also viewed as u16[PRE*MSUB]
__device__ u64   g_remv[WORDS];

// ---------------- kernels ----------------

// Fast path: one pass over scores, warp-aggregated stash of everything >= TC.
__global__ void __launch_bounds__(512) scan_k(const float4* __restrict__ sc) {
    int t = blockIdx.x*blockDim.x + threadIdx.x;
    float4 v = sc[t];
    unsigned m0 = __ballot_sync(0xffffffffu, v.x >= TC);
    unsigned m1 = __ballot_sync(0xffffffffu, v.y >= TC);
    unsigned m2 = __ballot_sync(0xffffffffu, v.z >= TC);
    unsigned m3 = __ballot_sync(0xffffffffu, v.w >= TC);
    int c0 = __popc(m0), c1 = __popc(m1), c2 = __popc(m2), c3 = __popc(m3);
    int tot = c0 + c1 + c2 + c3;
    if (tot == 0) return;
    int lane = threadIdx.x & 31;
    int base = 0;
    if (lane == 0) base = atomicAdd(&g_cand_count, tot);
    base = __shfl_sync(0xffffffffu, base, 0);
    unsigned lt = (1u << lane) - 1u;
    int off0 = base + __popc(m0 & lt);
    int off1 = base + c0 + __popc(m1 & lt);
    int off2 = base + c0 + c1 + __popc(m2 & lt);
    int off3 = base + c0 + c1 + c2 + __popc(m3 & lt);
    #pragma unroll
    for (int c = 0; c < 4; ++c) {
        float val = (c==0) ? v.x : (c==1) ? v.y : (c==2) ? v.z : v.w;
        int pos   = (c==0) ? off0 : (c==1) ? off1 : (c==2) ? off2 : off3;
        if (val >= TC && pos < CAP) {
            int g = 4*t + c;            // flat index in (A,S,H,W) layout
            int a = g / KK;
            int p = g - a*KK;
            unsigned i = (unsigned)(p*3 + a);
            g_cand[pos] = ((u64)__float_as_uint(val) << 32) |
                          (u64)(0xFFFFFFFFu - i);
        }
    }
}

// Exact fallback, single block. Early-exits (the normal case).
__global__ void __launch_bounds__(1024) fb_all_k(const float* __restrict__ sc) {
    int cnt0 = g_cand_count;
    if (cnt0 >= PRE && cnt0 <= CAP) return;

    __shared__ unsigned cs[1024];
    __shared__ unsigned ss[1024];
    __shared__ unsigned sh_hi, sh_need2, sh_T;
    int t = threadIdx.x;

    for (int o = t; o < 65536; o += 1024) { g_hist1[o] = 0u; g_hist2[o] = 0u; }
    __syncthreads();
    for (int i = t; i < NN; i += 1024) {
        unsigned b = __float_as_uint(sc[i]);
        atomicAdd(&g_hist1[b >> 16], 1u);
    }
    __syncthreads();
    {
        unsigned s = 0;
        for (int m = 0; m < 64; ++m) s += __ldcg(&g_hist1[t*64 + m]);
        cs[t] = s;
        int r = 1023 - t;
        ss[r] = s;
        __syncthreads();
        for (int off = 1; off < 1024; off <<= 1) {
            unsigned v = (r >= off) ? ss[r-off] : 0u;
            __syncthreads();
            ss[r] += v;
            __syncthreads();
        }
        unsigned need = PRE;
        unsigned incl = ss[r];
        unsigned above = incl - cs[t];
        if (above < need && need <= incl) {
            unsigned c = above;
            for (int m = 63; m >= 0; --m) {
                unsigned h = __ldcg(&g_hist1[t*64 + m]);
                if (c + h >= need) { sh_hi = (unsigned)(t*64 + m); sh_need2 = need - c; break; }
                c += h;
            }
        }
    }
    __syncthreads();
    unsigned hi = sh_hi;
    for (int i = t; i < NN; i += 1024) {
        unsigned b = __float_as_uint(sc[i]);
        if ((b >> 16) == hi) atomicAdd(&g_hist2[b & 0xFFFFu], 1u);
    }
    __syncthreads();
    {
        unsigned s = 0;
        for (int m = 0; m < 64; ++m) s += __ldcg(&g_hist2[t*64 + m]);
        cs[t] = s;
        int r = 1023 - t;
        ss[r] = s;
        __syncthreads();
        for (int off = 1; off < 1024; off <<= 1) {
            unsigned v = (r >= off) ? ss[r-off] : 0u;
            __syncthreads();
            ss[r] += v;
            __syncthreads();
        }
        unsigned need = sh_need2;
        unsigned incl = ss[r];
        unsigned above = incl - cs[t];
        if (above < need && need <= incl) {
            unsigned c = above;
            for (int m = 63; m >= 0; --m) {
                unsigned h = __ldcg(&g_hist2[t*64 + m]);
                if (c + h >= need) { sh_T = (hi << 16) | (unsigned)(t*64 + m); break; }
                c += h;
            }
        }
    }
    __syncthreads();
    if (t == 0) g_cand_count = 0;
    __syncthreads();
    unsigned T = sh_T;
    for (int i = t; i < NN; i += 1024) {
        unsigned b = __float_as_uint(sc[i]);
        if (b >= T) {
            int a = i / KK;
            int p = i - a*KK;
            unsigned id = (unsigned)(p*3 + a);
            int pos = atomicAdd(&g_cand_count, 1);
            if (pos < CAP)
                g_cand[pos] = ((u64)b << 32) | (u64)(0xFFFFFFFFu - id);
        }
    }
}

// All-pairs rank + fused box transform.
__global__ void __launch_bounds__(256) rank_k(const float* __restrict__ deltas,
                                              const float* __restrict__ ii,
                                              const float* __restrict__ anc) {
    __shared__ u64 tile[256];
    int cnt = g_cand_count; if (cnt > CAP) cnt = CAP;
    int i = blockIdx.x*256 + threadIdx.x;
    if (blockIdx.x*256 >= cnt) return;
    u64 my = (i < cnt) ? g_cand[i] : 0xFFFFFFFFFFFFFFFFull;
    int rank = 0;
    for (int base = 0; base < cnt; base += 256) {
        int j = base + threadIdx.x;
        tile[threadIdx.x] = (j < cnt) ? g_cand[j] : 0ull;   // 0 never counts
        __syncthreads();
        #pragma unroll 8
        for (int k = 0; k < 256; ++k) rank += (tile[k] > my) ? 1 : 0;
        __syncthreads();
    }
    if (i >= cnt || rank >= PRE) return;

    int idx = (int)(0xFFFFFFFFu - (unsigned)(my & 0xFFFFFFFFull));
    float score = __uint_as_float((unsigned)(my >> 32));
    int r = rank;
    int a = idx % 3;
    int p = idx / 3;
    int w = p % WW;
    int h = (p / WW) % HH;
    int s = p / (WW*HH);
    float shx = 4.0f * (float)w, shy = 4.0f * (float)h, shz = 4.0f * (float)s;
    float x1a = __fadd_rn(shx, anc[a*6+0]);
    float y1a = __fadd_rn(shy, anc[a*6+1]);
    float z1a = __fadd_rn(shz, anc[a*6+2]);
    float x2a = __fadd_rn(shx, anc[a*6+3]);
    float y2a = __fadd_rn(shy, anc[a*6+4]);
    float z2a = __fadd_rn(shz, anc[a*6+5]);
    float ww_ = __fadd_rn(__fsub_rn(x2a, x1a), 1.0f);
    float hh_ = __fadd_rn(__fsub_rn(y2a, y1a), 1.0f);
    float dd_ = __fadd_rn(__fsub_rn(z2a, z1a), 1.0f);
    float cx = __fadd_rn(x1a, __fmul_rn(0.5f, ww_));
    float cy = __fadd_rn(y1a, __fmul_rn(0.5f, hh_));
    float cz = __fadd_rn(z1a, __fmul_rn(0.5f, dd_));
    const float* dp = deltas + p;
    float dx = dp[(6*a+0)*KK];
    float dy = dp[(6*a+1)*KK];
    float dz = dp[(6*a+2)*KK];
    float dw = dp[(6*a+3)*KK];
    float dh = dp[(6*a+4)*KK];
    float dd = dp[(6*a+5)*KK];
    float pcx = __fadd_rn(__fmul_rn(dx, ww_), cx);
    float pcy = __fadd_rn(__fmul_rn(dy, hh_), cy);
    float pcz = __fadd_rn(__fmul_rn(dz, dd_), cz);
    float pw = __fmul_rn(expf(dw), ww_);
    float ph = __fmul_rn(expf(dh), hh_);
    float pd = __fmul_rn(expf(dd), dd_);
    float slices = ii[0], height = ii[1], width = ii[2], scale = ii[3];
    float wx = __fsub_rn(width, 1.0f);
    float hy = __fsub_rn(height, 1.0f);
    float sz = __fsub_rn(slices, 1.0f);
    float x1 = fminf(fmaxf(__fsub_rn(pcx, __fmul_rn(0.5f, pw)), 0.0f), wx);
    float y1 = fminf(fmaxf(__fsub_rn(pcy, __fmul_rn(0.5f, ph)), 0.0f), hy);
    float z1 = fminf(fmaxf(__fsub_rn(pcz, __fmul_rn(0.5f, pd)), 0.0f), sz);
    float x2 = fminf(fmaxf(__fsub_rn(__fadd_rn(pcx, __fmul_rn(0.5f, pw)), 1.0f), 0.0f), wx);
    float y2 = fminf(fmaxf(__fsub_rn(__fadd_rn(pcy, __fmul_rn(0.5f, ph)), 1.0f), 0.0f), hy);
    float z2 = fminf(fmaxf(__fsub_rn(__fadd_rn(pcz, __fmul_rn(0.5f, pd)), 1.0f), 0.0f), sz);
    float ss_ = __fadd_rn(__fsub_rn(x2, x1), 1.0f);
    float xc = __fadd_rn(x1, __fmul_rn(ss_, 0.5f));
    float yc = __fadd_rn(y1, __fmul_rn(ss_, 0.5f));
    float zc = __fadd_rn(z1, __fmul_rn(ss_, 0.5f));
    float minsz = __fmul_rn(8.0f, scale);
    int valid = (ss_ >= minsz) && (xc < width) && (yc < height) && (zc < slices);
    float vy = __fadd_rn(__fsub_rn(y2, y1), 1.0f);
    float vz = __fadd_rn(__fsub_rn(z2, z1), 1.0f);
    float vol = __fmul_rn(__fmul_rn(ss_, vy), vz);
    g_bx1[r] = x1; g_by1[r] = y1; g_bz1[r] = z1;
    g_bx2[r] = x2; g_by2[r] = y2; g_bz2[r] = z2;
    g_volv[r] = vol;
    g_valid[r] = valid;
    g_order[r] = idx;
    g_score[r] = score;
}

// IoU mask, fine-grained: one thread per (row, 16-column chunk).
// 2000*128 = 256000 threads. Lower-triangle chunks early-out (store 0).
// Stored as u16; 16|64 alignment makes the u16 view identical to the u64
// words final_k consumes (little-endian).
__global__ void __launch_bounds__(256) mask_k() {
    int gid = blockIdx.x*256 + threadIdx.x;
    if (gid >= PRE*MSUB) return;
    int r   = gid >> 7;          // row
    int sub = gid & (MSUB-1);    // 16-col chunk
    unsigned short* m16 = (unsigned short*)g_mask;
    int j0 = sub * 16;
    unsigned bits = 0u;
    if (j0 + 15 > r) {
        float x1 = g_bx1[r], y1 = g_by1[r], z1 = g_bz1[r];
        float x2 = g_bx2[r], y2 = g_by2[r], z2 = g_bz2[r];
        float vr = g_volv[r];
        #pragma unroll
        for (int k = 0; k < 16; ++k) {
            int j = j0 + k;
            if (j < PRE && j > r) {
                float iw = fmaxf(__fadd_rn(__fsub_rn(fminf(x2, __ldg(&g_bx2[j])), fmaxf(x1, __ldg(&g_bx1[j]))), 1.0f), 0.0f);
                float ih = fmaxf(__fadd_rn(__fsub_rn(fminf(y2, __ldg(&g_by2[j])), fmaxf(y1, __ldg(&g_by1[j]))), 1.0f), 0.0f);
                float id = fmaxf(__fadd_rn(__fsub_rn(fminf(z2, __ldg(&g_bz2[j])), fmaxf(z1, __ldg(&g_bz1[j]))), 1.0f), 0.0f);
                float inter = __fmul_rn(__fmul_rn(iw, ih), id);
                float denom = __fsub_rn(__fadd_rn(vr, __ldg(&g_volv[j])), inter);
                float iou = __fdiv_rn(inter, denom);
                if (iou > NMS_T) bits |= (1u << k);
            }
        }
    }
    m16[gid] = (unsigned short)bits;
}

__device__ __forceinline__ void fill_one(float* out, int i, int pos) {
    int base = pos*7;
    out[base+0] = 0.0f;
    out[base+1] = g_bx1[i];
    out[base+2] = g_by1[i];
    out[base+3] = g_bz1[i];
    out[base+4] = g_bx2[i];
    out[base+5] = g_by2[i];
    out[base+6] = g_bz2[i];
    out[POST*7 + pos] = g_score[i];          // 2100..2399
    out[POST*8 + pos] = (float)g_order[i];   // 2400..2699
    out[POST*9 + pos] = 1.0f;                // 2700..2999
}

// Merged NMS-reduce + output, 512 threads. Warp 0: serial greedy reduce with
// register double-buffering, 16-bit decide window in the owning lane, and a
// 5-level OR tree to apply accepted rows. Warps 1..15 init the output buffer.
__global__ void __launch_bounds__(512) final_k(float* __restrict__ out, int out_size) {
    __shared__ int sc[512];
    __shared__ u64 rw[WORDS];
    int t = threadIdx.x;

    if (t < 32) {
        int lane = t;
        u64 rm = 0ull;
        #pragma unroll
        for (int b = 0; b < 64; ++b) {
            int j = lane*64 + b;
            int inval = (j < PRE) ? (g_valid[j] ? 0 : 1) : 1;
            rm |= ((u64)inval) << b;
        }
        const int NCH = (PRE + 15) / 16;    // 125 chunks
        u64 v[16], nx[16];
        #pragma unroll
        for (int b = 0; b < 16; ++b)
            v[b] = g_mask[(size_t)b*WORDS + lane];
        for (int c = 0; c < NCH; ++c) {
            int nbase = (c + 1) * 16;
            #pragma unroll
            for (int b = 0; b < 16; ++b) {
                int row = nbase + b;
                nx[b] = (row < PRE) ? g_mask[(size_t)row*WORDS + lane] : 0ull;
            }
            int w  = (c * 16) >> 6;
            int sh = (c * 16) & 63;
            unsigned acc = 0u;
            if (lane == w) {
                // 32-bit decide window: decisions only read bits [sh, sh+16)
                unsigned w16 = (unsigned)(rm >> sh) & 0xFFFFu;
                unsigned vw[16];
                #pragma unroll
                for (int b = 0; b < 16; ++b)
                    vw[b] = (unsigned)(v[b] >> sh) & 0xFFFFu;
                #pragma unroll
                for (int b = 0; b < 16; ++b) {
                    unsigned sup = (w16 >> b) & 1u;
                    acc |= (sup ^ 1u) << b;
                    w16 |= sup ? 0u : vw[b];
                }
            }
            acc = __shfl_sync(0xffffffffu, acc, w);
            // apply accepted rows via OR tree (all lanes, full width)
            {
                u64 s0  = ((acc>>0)&1u)  ? v[0]  : 0ull;
                u64 s1  = ((acc>>1)&1u)  ? v[1]  : 0ull;
                u64 s2  = ((acc>>2)&1u)  ? v[2]  : 0ull;
                u64 s3  = ((acc>>3)&1u)  ? v[3]  : 0ull;
                u64 s4  = ((acc>>4)&1u)  ? v[4]  : 0ull;
                u64 s5  = ((acc>>5)&1u)  ? v[5]  : 0ull;
                u64 s6  = ((acc>>6)&1u)  ? v[6]  : 0ull;
                u64 s7  = ((acc>>7)&1u)  ? v[7]  : 0ull;
                u64 s8  = ((acc>>8)&1u)  ? v[8]  : 0ull;
                u64 s9  = ((acc>>9)&1u)  ? v[9]  : 0ull;
                u64 s10 = ((acc>>10)&1u) ? v[10] : 0ull;
                u64 s11 = ((acc>>11)&1u) ? v[11] : 0ull;
                u64 s12 = ((acc>>12)&1u) ? v[12] : 0ull;
                u64 s13 = ((acc>>13)&1u) ? v[13] : 0ull;
                u64 s14 = ((acc>>14)&1u) ? v[14] : 0ull;
                u64 s15 = ((acc>>15)&1u) ? v[15] : 0ull;
                u64 a0 = (s0|s1)   | (s2|s3);
                u64 a1 = (s4|s5)   | (s6|s7);
                u64 a2 = (s8|s9)   | (s10|s11);
                u64 a3 = (s12|s13) | (s14|s15);
                rm |= (a0|a1) | (a2|a3);
            }
            #pragma unroll
            for (int b = 0; b < 16; ++b) v[b] = nx[b];
        }
        rw[lane] = rm;
    } else {
        for (int o = t - 32; o < POST*8; o += 480) if (o < out_size) out[o] = 0.0f;
        for (int o = t - 32; o < POST; o += 480) {
            if (POST*8 + o < out_size) out[POST*8 + o] = -1.0f;
            if (POST*9 + o < out_size) out[POST*9 + o] = 0.0f;
        }
    }
    __syncthreads();

    int kk[4];
    int ksum = 0;
    #pragma unroll
    for (int c = 0; c < 4; ++c) {
        int i = 4*t + c;
        int k = 0;
        if (i < PRE) k = (g_valid[i] && !((rw[i>>6] >> (i & 63)) & 1ull)) ? 1 : 0;
        kk[c] = k;
        ksum += k;
    }
    sc[t] = ksum;
    __syncthreads();
    for (int off = 1; off < 512; off <<= 1) {
        int v = (t >= off) ? sc[t-off] : 0;
        __syncthreads();
        sc[t] += v;
        __syncthreads();
    }
    int pos = sc[t] - ksum;
    if (out_size >= POST*10) {
        #pragma unroll
        for (int c = 0; c < 4; ++c) {
            if (kk[c] && pos < POST) fill_one(out, 4*t + c, pos);
            pos += kk[c];
        }
    }
    if (t == 0) g_cand_count = 0;   // clean state for next graph replay
}

// ---------------- launch ----------------
extern "C" void kernel_launch(void* const* d_in, const int* in_sizes, int n_in,
                              void* d_out, int out_size) {
    const float* scores  = (const float*)d_in[0];
    const float* deltas  = (const float*)d_in[1];
    const float* iminfo  = (const float*)d_in[2];
    const float* anchors = (const float*)d_in[3];
    float* out = (float*)d_out;

    scan_k<<<768, 512>>>((const float4*)scores);       // NN/4 threads exactly
    fb_all_k<<<1, 1024>>>(scores);                     // early-exits normally
    rank_k<<<CAP/256, 256>>>(deltas, iminfo, anchors);
    mask_k<<<(PRE*MSUB + 255)/256, 256>>>();
    final_k<<<1, 512>>>(out, out_size);
}

// round 10
// speedup vs baseline: 1.1833x; 1.1833x over previous
#include <cuda_runtime.h>
#include <cstdint>

// Problem constants
#define AN 3
#define SSZ 32
#define HH 128
#define WW 128
#define KK (SSZ*HH*WW)        // 524288 spatial positions
#define NN (KK*AN)            // 1572864 total anchors
#define PRE 2000
#define POST 300
#define WORDS 32              // 2048 bits >= PRE
#define CAP 4096
#define NMS_T 0.7f
#define TC 0.99834f           // static stash threshold (fast path)

typedef unsigned long long u64;

// ---------------- device state ----------------
__device__ unsigned int g_hist1[65536];
__device__ unsigned int g_hist2[65536];
__device__ int          g_cand_count;      // zero-init; reset by final_k
__device__ u64          g_cand[CAP];

__device__ int   g_order[PRE];
__device__ float g_score[PRE];
__device__ float g_bx1[PRE], g_by1[PRE], g_bz1[PRE];
__device__ float g_bx2[PRE], g_by2[PRE], g_bz2[PRE];
__device__ float g_volv[PRE];
__device__ int   g_valid[PRE];
__device__ u64   g_mask[PRE*WORDS];        // u32 view: [PRE*64]
__device__ u64   g_remv[WORDS];

// ---------------- kernels ----------------

// Fast path: one pass over scores, warp-aggregated stash of everything >= TC.
__global__ void __launch_bounds__(512) scan_k(const float4* __restrict__ sc) {
    int t = blockIdx.x*blockDim.x + threadIdx.x;
    float4 v = sc[t];
    unsigned m0 = __ballot_sync(0xffffffffu, v.x >= TC);
    unsigned m1 = __ballot_sync(0xffffffffu, v.y >= TC);
    unsigned m2 = __ballot_sync(0xffffffffu, v.z >= TC);
    unsigned m3 = __ballot_sync(0xffffffffu, v.w >= TC);
    int c0 = __popc(m0), c1 = __popc(m1), c2 = __popc(m2), c3 = __popc(m3);
    int tot = c0 + c1 + c2 + c3;
    if (tot == 0) return;
    int lane = threadIdx.x & 31;
    int base = 0;
    if (lane == 0) base = atomicAdd(&g_cand_count, tot);
    base = __shfl_sync(0xffffffffu, base, 0);
    unsigned lt = (1u << lane) - 1u;
    int off0 = base + __popc(m0 & lt);
    int off1 = base + c0 + __popc(m1 & lt);
    int off2 = base + c0 + c1 + __popc(m2 & lt);
    int off3 = base + c0 + c1 + c2 + __popc(m3 & lt);
    #pragma unroll
    for (int c = 0; c < 4; ++c) {
        float val = (c==0) ? v.x : (c==1) ? v.y : (c==2) ? v.z : v.w;
        int pos   = (c==0) ? off0 : (c==1) ? off1 : (c==2) ? off2 : off3;
        if (val >= TC && pos < CAP) {
            int g = 4*t + c;            // flat index in (A,S,H,W) layout
            int a = g / KK;
            int p = g - a*KK;
            unsigned i = (unsigned)(p*3 + a);
            g_cand[pos] = ((u64)__float_as_uint(val) << 32) |
                          (u64)(0xFFFFFFFFu - i);
        }
    }
}

// Exact fallback, single block. Early-exits (the normal case).
__global__ void __launch_bounds__(1024) fb_all_k(const float* __restrict__ sc) {
    int cnt0 = g_cand_count;
    if (cnt0 >= PRE && cnt0 <= CAP) return;

    __shared__ unsigned cs[1024];
    __shared__ unsigned ss[1024];
    __shared__ unsigned sh_hi, sh_need2, sh_T;
    int t = threadIdx.x;

    for (int o = t; o < 65536; o += 1024) { g_hist1[o] = 0u; g_hist2[o] = 0u; }
    __syncthreads();
    for (int i = t; i < NN; i += 1024) {
        unsigned b = __float_as_uint(sc[i]);
        atomicAdd(&g_hist1[b >> 16], 1u);
    }
    __syncthreads();
    {
        unsigned s = 0;
        for (int m = 0; m < 64; ++m) s += __ldcg(&g_hist1[t*64 + m]);
        cs[t] = s;
        int r = 1023 - t;
        ss[r] = s;
        __syncthreads();
        for (int off = 1; off < 1024; off <<= 1) {
            unsigned v = (r >= off) ? ss[r-off] : 0u;
            __syncthreads();
            ss[r] += v;
            __syncthreads();
        }
        unsigned need = PRE;
        unsigned incl = ss[r];
        unsigned above = incl - cs[t];
        if (above < need && need <= incl) {
            unsigned c = above;
            for (int m = 63; m >= 0; --m) {
                unsigned h = __ldcg(&g_hist1[t*64 + m]);
                if (c + h >= need) { sh_hi = (unsigned)(t*64 + m); sh_need2 = need - c; break; }
                c += h;
            }
        }
    }
    __syncthreads();
    unsigned hi = sh_hi;
    for (int i = t; i < NN; i += 1024) {
        unsigned b = __float_as_uint(sc[i]);
        if ((b >> 16) == hi) atomicAdd(&g_hist2[b & 0xFFFFu], 1u);
    }
    __syncthreads();
    {
        unsigned s = 0;
        for (int m = 0; m < 64; ++m) s += __ldcg(&g_hist2[t*64 + m]);
        cs[t] = s;
        int r = 1023 - t;
        ss[r] = s;
        __syncthreads();
        for (int off = 1; off < 1024; off <<= 1) {
            unsigned v = (r >= off) ? ss[r-off] : 0u;
            __syncthreads();
            ss[r] += v;
            __syncthreads();
        }
        unsigned need = sh_need2;
        unsigned incl = ss[r];
        unsigned above = incl - cs[t];
        if (above < need && need <= incl) {
            unsigned c = above;
            for (int m = 63; m >= 0; --m) {
                unsigned h = __ldcg(&g_hist2[t*64 + m]);
                if (c + h >= need) { sh_T = (hi << 16) | (unsigned)(t*64 + m); break; }
                c += h;
            }
        }
    }
    __syncthreads();
    if (t == 0) g_cand_count = 0;
    __syncthreads();
    unsigned T = sh_T;
    for (int i = t; i < NN; i += 1024) {
        unsigned b = __float_as_uint(sc[i]);
        if (b >= T) {
            int a = i / KK;
            int p = i - a*KK;
            unsigned id = (unsigned)(p*3 + a);
            int pos = atomicAdd(&g_cand_count, 1);
            if (pos < CAP)
                g_cand[pos] = ((u64)b << 32) | (u64)(0xFFFFFFFFu - id);
        }
    }
}

// All-pairs rank + fused box transform.
__global__ void __launch_bounds__(256) rank_k(const float* __restrict__ deltas,
                                              const float* __restrict__ ii,
                                              const float* __restrict__ anc) {
    __shared__ u64 tile[256];
    int cnt = g_cand_count; if (cnt > CAP) cnt = CAP;
    int i = blockIdx.x*256 + threadIdx.x;
    if (blockIdx.x*256 >= cnt) return;
    u64 my = (i < cnt) ? g_cand[i] : 0xFFFFFFFFFFFFFFFFull;
    int rank = 0;
    for (int base = 0; base < cnt; base += 256) {
        int j = base + threadIdx.x;
        tile[threadIdx.x] = (j < cnt) ? g_cand[j] : 0ull;   // 0 never counts
        __syncthreads();
        #pragma unroll 8
        for (int k = 0; k < 256; ++k) rank += (tile[k] > my) ? 1 : 0;
        __syncthreads();
    }
    if (i >= cnt || rank >= PRE) return;

    int idx = (int)(0xFFFFFFFFu - (unsigned)(my & 0xFFFFFFFFull));
    float score = __uint_as_float((unsigned)(my >> 32));
    int r = rank;
    int a = idx % 3;
    int p = idx / 3;
    int w = p % WW;
    int h = (p / WW) % HH;
    int s = p / (WW*HH);
    float shx = 4.0f * (float)w, shy = 4.0f * (float)h, shz = 4.0f * (float)s;
    float x1a = __fadd_rn(shx, anc[a*6+0]);
    float y1a = __fadd_rn(shy, anc[a*6+1]);
    float z1a = __fadd_rn(shz, anc[a*6+2]);
    float x2a = __fadd_rn(shx, anc[a*6+3]);
    float y2a = __fadd_rn(shy, anc[a*6+4]);
    float z2a = __fadd_rn(shz, anc[a*6+5]);
    float ww_ = __fadd_rn(__fsub_rn(x2a, x1a), 1.0f);
    float hh_ = __fadd_rn(__fsub_rn(y2a, y1a), 1.0f);
    float dd_ = __fadd_rn(__fsub_rn(z2a, z1a), 1.0f);
    float cx = __fadd_rn(x1a, __fmul_rn(0.5f, ww_));
    float cy = __fadd_rn(y1a, __fmul_rn(0.5f, hh_));
    float cz = __fadd_rn(z1a, __fmul_rn(0.5f, dd_));
    const float* dp = deltas + p;
    float dx = dp[(6*a+0)*KK];
    float dy = dp[(6*a+1)*KK];
    float dz = dp[(6*a+2)*KK];
    float dw = dp[(6*a+3)*KK];
    float dh = dp[(6*a+4)*KK];
    float dd = dp[(6*a+5)*KK];
    float pcx = __fadd_rn(__fmul_rn(dx, ww_), cx);
    float pcy = __fadd_rn(__fmul_rn(dy, hh_), cy);
    float pcz = __fadd_rn(__fmul_rn(dz, dd_), cz);
    float pw = __fmul_rn(expf(dw), ww_);
    float ph = __fmul_rn(expf(dh), hh_);
    float pd = __fmul_rn(expf(dd), dd_);
    float slices = ii[0], height = ii[1], width = ii[2], scale = ii[3];
    float wx = __fsub_rn(width, 1.0f);
    float hy = __fsub_rn(height, 1.0f);
    float sz = __fsub_rn(slices, 1.0f);
    float x1 = fminf(fmaxf(__fsub_rn(pcx, __fmul_rn(0.5f, pw)), 0.0f), wx);
    float y1 = fminf(fmaxf(__fsub_rn(pcy, __fmul_rn(0.5f, ph)), 0.0f), hy);
    float z1 = fminf(fmaxf(__fsub_rn(pcz, __fmul_rn(0.5f, pd)), 0.0f), sz);
    float x2 = fminf(fmaxf(__fsub_rn(__fadd_rn(pcx, __fmul_rn(0.5f, pw)), 1.0f), 0.0f), wx);
    float y2 = fminf(fmaxf(__fsub_rn(__fadd_rn(pcy, __fmul_rn(0.5f, ph)), 1.0f), 0.0f), hy);
    float z2 = fminf(fmaxf(__fsub_rn(__fadd_rn(pcz, __fmul_rn(0.5f, pd)), 1.0f), 0.0f), sz);
    float ss_ = __fadd_rn(__fsub_rn(x2, x1), 1.0f);
    float xc = __fadd_rn(x1, __fmul_rn(ss_, 0.5f));
    float yc = __fadd_rn(y1, __fmul_rn(ss_, 0.5f));
    float zc = __fadd_rn(z1, __fmul_rn(ss_, 0.5f));
    float minsz = __fmul_rn(8.0f, scale);
    int valid = (ss_ >= minsz) && (xc < width) && (yc < height) && (zc < slices);
    float vy = __fadd_rn(__fsub_rn(y2, y1), 1.0f);
    float vz = __fadd_rn(__fsub_rn(z2, z1), 1.0f);
    float vol = __fmul_rn(__fmul_rn(ss_, vy), vz);
    g_bx1[r] = x1; g_by1[r] = y1; g_bz1[r] = z1;
    g_bx2[r] = x2; g_by2[r] = y2; g_bz2[r] = z2;
    g_volv[r] = vol;
    g_valid[r] = valid;
    g_order[r] = idx;
    g_score[r] = score;
}

// IoU mask, tiled (128 rows x 32 cols): thread = one row, columns in smem
// (broadcast reads), row data in registers -> ~0.25 global loads per IoU.
// Output is one u32 per thread; the u32 view of g_mask matches the u64 words
// final_k consumes (little-endian). Blocks entirely in the lower triangle
// store zeros and exit. Division is skipped when inter == 0 (iou == 0 exactly).
__global__ void __launch_bounds__(128) mask_k() {
    __shared__ float cx1[32], cy1[32], cz1[32], cx2[32], cy2[32], cz2[32], cv[32];
    int chunk = blockIdx.x;             // col chunk: cols [32*chunk, 32*chunk+32)
    int rb    = blockIdx.y;             // rowblock of 128
    int t = threadIdx.x;
    int r = rb*128 + t;
    unsigned* m32 = (unsigned*)g_mask;
    // whole block in lower triangle (every row >= every col) -> zeros
    if (rb*128 >= chunk*32 + 32) {
        if (r < PRE) m32[r*64 + chunk] = 0u;
        return;
    }
    if (t < 32) {
        int c = chunk*32 + t;
        if (c < PRE) {
            cx1[t] = g_bx1[c]; cy1[t] = g_by1[c]; cz1[t] = g_bz1[c];
            cx2[t] = g_bx2[c]; cy2[t] = g_by2[c]; cz2[t] = g_bz2[c];
            cv[t]  = g_volv[c];
        }
    }
    __syncthreads();
    if (r >= PRE) return;
    float x1 = g_bx1[r], y1 = g_by1[r], z1 = g_bz1[r];
    float x2 = g_bx2[r], y2 = g_by2[r], z2 = g_bz2[r];
    float vr = g_volv[r];
    unsigned bits = 0u;
    #pragma unroll 8
    for (int k = 0; k < 32; ++k) {
        int j = chunk*32 + k;
        if (j < PRE && j > r) {
            float iw = fmaxf(__fadd_rn(__fsub_rn(fminf(x2, cx2[k]), fmaxf(x1, cx1[k])), 1.0f), 0.0f);
            float ih = fmaxf(__fadd_rn(__fsub_rn(fminf(y2, cy2[k]), fmaxf(y1, cy1[k])), 1.0f), 0.0f);
            float id = fmaxf(__fadd_rn(__fsub_rn(fminf(z2, cz2[k]), fmaxf(z1, cz1[k])), 1.0f), 0.0f);
            float inter = __fmul_rn(__fmul_rn(iw, ih), id);
            if (inter > 0.0f) {
                float denom = __fsub_rn(__fadd_rn(vr, cv[k]), inter);
                float iou = __fdiv_rn(inter, denom);
                if (iou > NMS_T) bits |= (1u << k);
            }
        }
    }
    m32[r*64 + chunk] = bits;
}

__device__ __forceinline__ void fill_one(float* out, int i, int pos) {
    int base = pos*7;
    out[base+0] = 0.0f;
    out[base+1] = g_bx1[i];
    out[base+2] = g_by1[i];
    out[base+3] = g_bz1[i];
    out[base+4] = g_bx2[i];
    out[base+5] = g_by2[i];
    out[base+6] = g_bz2[i];
    out[POST*7 + pos] = g_score[i];          // 2100..2399
    out[POST*8 + pos] = (float)g_order[i];   // 2400..2699
    out[POST*9 + pos] = 1.0f;                // 2700..2999
}

// Merged NMS-reduce + output, 512 threads. Warp 0: serial greedy reduce with
// register double-buffering, 16-bit decide window in the owning lane, and a
// 5-level OR tree to apply accepted rows. Warps 1..15 init the output buffer.
__global__ void __launch_bounds__(512) final_k(float* __restrict__ out, int out_size) {
    __shared__ int sc[512];
    __shared__ u64 rw[WORDS];
    int t = threadIdx.x;

    if (t < 32) {
        int lane = t;
        u64 rm = 0ull;
        #pragma unroll
        for (int b = 0; b < 64; ++b) {
            int j = lane*64 + b;
            int inval = (j < PRE) ? (g_valid[j] ? 0 : 1) : 1;
            rm |= ((u64)inval) << b;
        }
        const int NCH = (PRE + 15) / 16;    // 125 chunks
        u64 v[16], nx[16];
        #pragma unroll
        for (int b = 0; b < 16; ++b)
            v[b] = g_mask[(size_t)b*WORDS + lane];
        for (int c = 0; c < NCH; ++c) {
            int nbase = (c + 1) * 16;
            #pragma unroll
            for (int b = 0; b < 16; ++b) {
                int row = nbase + b;
                nx[b] = (row < PRE) ? g_mask[(size_t)row*WORDS + lane] : 0ull;
            }
            int w  = (c * 16) >> 6;
            int sh = (c * 16) & 63;
            unsigned acc = 0u;
            if (lane == w) {
                unsigned w16 = (unsigned)(rm >> sh) & 0xFFFFu;
                unsigned vw[16];
                #pragma unroll
                for (int b = 0; b < 16; ++b)
                    vw[b] = (unsigned)(v[b] >> sh) & 0xFFFFu;
                #pragma unroll
                for (int b = 0; b < 16; ++b) {
                    unsigned sup = (w16 >> b) & 1u;
                    acc |= (sup ^ 1u) << b;
                    w16 |= sup ? 0u : vw[b];
                }
            }
            acc = __shfl_sync(0xffffffffu, acc, w);
            {
                u64 s0  = ((acc>>0)&1u)  ? v[0]  : 0ull;
                u64 s1  = ((acc>>1)&1u)  ? v[1]  : 0ull;
                u64 s2  = ((acc>>2)&1u)  ? v[2]  : 0ull;
                u64 s3  = ((acc>>3)&1u)  ? v[3]  : 0ull;
                u64 s4  = ((acc>>4)&1u)  ? v[4]  : 0ull;
                u64 s5  = ((acc>>5)&1u)  ? v[5]  : 0ull;
                u64 s6  = ((acc>>6)&1u)  ? v[6]  : 0ull;
                u64 s7  = ((acc>>7)&1u)  ? v[7]  : 0ull;
                u64 s8  = ((acc>>8)&1u)  ? v[8]  : 0ull;
                u64 s9  = ((acc>>9)&1u)  ? v[9]  : 0ull;
                u64 s10 = ((acc>>10)&1u) ? v[10] : 0ull;
                u64 s11 = ((acc>>11)&1u) ? v[11] : 0ull;
                u64 s12 = ((acc>>12)&1u) ? v[12] : 0ull;
                u64 s13 = ((acc>>13)&1u) ? v[13] : 0ull;
                u64 s14 = ((acc>>14)&1u) ? v[14] : 0ull;
                u64 s15 = ((acc>>15)&1u) ? v[15] : 0ull;
                u64 a0 = (s0|s1)   | (s2|s3);
                u64 a1 = (s4|s5)   | (s6|s7);
                u64 a2 = (s8|s9)   | (s10|s11);
                u64 a3 = (s12|s13) | (s14|s15);
                rm |= (a0|a1) | (a2|a3);
            }
            #pragma unroll
            for (int b = 0; b < 16; ++b) v[b] = nx[b];
        }
        rw[lane] = rm;
    } else {
        for (int o = t - 32; o < POST*8; o += 480) if (o < out_size) out[o] = 0.0f;
        for (int o = t - 32; o < POST; o += 480) {
            if (POST*8 + o < out_size) out[POST*8 + o] = -1.0f;
            if (POST*9 + o < out_size) out[POST*9 + o] = 0.0f;
        }
    }
    __syncthreads();

    int kk[4];
    int ksum = 0;
    #pragma unroll
    for (int c = 0; c < 4; ++c) {
        int i = 4*t + c;
        int k = 0;
        if (i < PRE) k = (g_valid[i] && !((rw[i>>6] >> (i & 63)) & 1ull)) ? 1 : 0;
        kk[c] = k;
        ksum += k;
    }
    sc[t] = ksum;
    __syncthreads();
    for (int off = 1; off < 512; off <<= 1) {
        int v = (t >= off) ? sc[t-off] : 0;
        __syncthreads();
        sc[t] += v;
        __syncthreads();
    }
    int pos = sc[t] - ksum;
    if (out_size >= POST*10) {
        #pragma unroll
        for (int c = 0; c < 4; ++c) {
            if (kk[c] && pos < POST) fill_one(out, 4*t + c, pos);
            pos += kk[c];
        }
    }
    if (t == 0) g_cand_count = 0;   // clean state for next graph replay
}

// ---------------- launch ----------------
extern "C" void kernel_launch(void* const* d_in, const int* in_sizes, int n_in,
                              void* d_out, int out_size) {
    const float* scores  = (const float*)d_in[0];
    const float* deltas  = (const float*)d_in[1];
    const float* iminfo  = (const float*)d_in[2];
    const float* anchors = (const float*)d_in[3];
    float* out = (float*)d_out;

    scan_k<<<768, 512>>>((const float4*)scores);       // NN/4 threads exactly
    fb_all_k<<<1, 1024>>>(scores);                     // early-exits normally
    rank_k<<<CAP/256, 256>>>(deltas, iminfo, anchors);
    mask_k<<<dim3(64, (PRE + 127)/128), 128>>>();
    final_k<<<1, 512>>>(out, out_size);
}

// round 12
// speedup vs baseline: 1.6606x; 1.4033x over previous
#include <cuda_runtime.h>
#include <cstdint>

// Problem constants
#define AN 3
#define SSZ 32
#define HH 128
#define WW 128
#define KK (SSZ*HH*WW)        // 524288 spatial positions
#define NN (KK*AN)            // 1572864 total anchors
#define PRE 2000
#define POST 300
#define WORDS 32              // 2048 bits >= PRE
#define CAP 4096
#define NMS_T 0.7f
#define TC 0.99834f           // static stash threshold (fast path)

typedef unsigned long long u64;

// ---------------- device state ----------------
__device__ unsigned int g_hist1[65536];
__device__ unsigned int g_hist2[65536];
__device__ int          g_cand_count;      // zero-init; reset by final_k
__device__ u64          g_cand[CAP];
__device__ int          g_rank[CAP];       // zeroed by scan_k each call

__device__ int   g_order[PRE];
__device__ float g_score[PRE];
__device__ float g_bx1[PRE], g_by1[PRE], g_bz1[PRE];
__device__ float g_bx2[PRE], g_by2[PRE], g_bz2[PRE];
__device__ float g_volv[PRE];
__device__ int   g_valid[PRE];
__device__ u64   g_mask[PRE*WORDS];        // u32 view: [PRE*64]

// ---------------- kernels ----------------

// Fast path: one pass over scores, warp-aggregated stash of everything >= TC.
// Also zeros g_rank for this invocation.
__global__ void __launch_bounds__(512) scan_k(const float4* __restrict__ sc) {
    int t = blockIdx.x*blockDim.x + threadIdx.x;
    if (t < CAP) g_rank[t] = 0;
    float4 v = sc[t];
    unsigned m0 = __ballot_sync(0xffffffffu, v.x >= TC);
    unsigned m1 = __ballot_sync(0xffffffffu, v.y >= TC);
    unsigned m2 = __ballot_sync(0xffffffffu, v.z >= TC);
    unsigned m3 = __ballot_sync(0xffffffffu, v.w >= TC);
    int c0 = __popc(m0), c1 = __popc(m1), c2 = __popc(m2), c3 = __popc(m3);
    int tot = c0 + c1 + c2 + c3;
    if (tot == 0) return;
    int lane = threadIdx.x & 31;
    int base = 0;
    if (lane == 0) base = atomicAdd(&g_cand_count, tot);
    base = __shfl_sync(0xffffffffu, base, 0);
    unsigned lt = (1u << lane) - 1u;
    int off0 = base + __popc(m0 & lt);
    int off1 = base + c0 + __popc(m1 & lt);
    int off2 = base + c0 + c1 + __popc(m2 & lt);
    int off3 = base + c0 + c1 + c2 + __popc(m3 & lt);
    #pragma unroll
    for (int c = 0; c < 4; ++c) {
        float val = (c==0) ? v.x : (c==1) ? v.y : (c==2) ? v.z : v.w;
        int pos   = (c==0) ? off0 : (c==1) ? off1 : (c==2) ? off2 : off3;
        if (val >= TC && pos < CAP) {
            int g = 4*t + c;            // flat index in (A,S,H,W) layout
            int a = g / KK;
            int p = g - a*KK;
            unsigned i = (unsigned)(p*3 + a);
            g_cand[pos] = ((u64)__float_as_uint(val) << 32) |
                          (u64)(0xFFFFFFFFu - i);
        }
    }
}

// Exact fallback, single block. Early-exits (the normal case).
__global__ void __launch_bounds__(1024) fb_all_k(const float* __restrict__ sc) {
    int cnt0 = g_cand_count;
    if (cnt0 >= PRE && cnt0 <= CAP) return;

    __shared__ unsigned cs[1024];
    __shared__ unsigned ss[1024];
    __shared__ unsigned sh_hi, sh_need2, sh_T;
    int t = threadIdx.x;

    for (int o = t; o < 65536; o += 1024) { g_hist1[o] = 0u; g_hist2[o] = 0u; }
    __syncthreads();
    for (int i = t; i < NN; i += 1024) {
        unsigned b = __float_as_uint(sc[i]);
        atomicAdd(&g_hist1[b >> 16], 1u);
    }
    __syncthreads();
    {
        unsigned s = 0;
        for (int m = 0; m < 64; ++m) s += __ldcg(&g_hist1[t*64 + m]);
        cs[t] = s;
        int r = 1023 - t;
        ss[r] = s;
        __syncthreads();
        for (int off = 1; off < 1024; off <<= 1) {
            unsigned v = (r >= off) ? ss[r-off] : 0u;
            __syncthreads();
            ss[r] += v;
            __syncthreads();
        }
        unsigned need = PRE;
        unsigned incl = ss[r];
        unsigned above = incl - cs[t];
        if (above < need && need <= incl) {
            unsigned c = above;
            for (int m = 63; m >= 0; --m) {
                unsigned h = __ldcg(&g_hist1[t*64 + m]);
                if (c + h >= need) { sh_hi = (unsigned)(t*64 + m); sh_need2 = need - c; break; }
                c += h;
            }
        }
    }
    __syncthreads();
    unsigned hi = sh_hi;
    for (int i = t; i < NN; i += 1024) {
        unsigned b = __float_as_uint(sc[i]);
        if ((b >> 16) == hi) atomicAdd(&g_hist2[b & 0xFFFFu], 1u);
    }
    __syncthreads();
    {
        unsigned s = 0;
        for (int m = 0; m < 64; ++m) s += __ldcg(&g_hist2[t*64 + m]);
        cs[t] = s;
        int r = 1023 - t;
        ss[r] = s;
        __syncthreads();
        for (int off = 1; off < 1024; off <<= 1) {
            unsigned v = (r >= off) ? ss[r-off] : 0u;
            __syncthreads();
            ss[r] += v;
            __syncthreads();
        }
        unsigned need = sh_need2;
        unsigned incl = ss[r];
        unsigned above = incl - cs[t];
        if (above < need && need <= incl) {
            unsigned c = above;
            for (int m = 63; m >= 0; --m) {
                unsigned h = __ldcg(&g_hist2[t*64 + m]);
                if (c + h >= need) { sh_T = (hi << 16) | (unsigned)(t*64 + m); break; }
                c += h;
            }
        }
    }
    __syncthreads();
    if (t == 0) g_cand_count = 0;
    __syncthreads();
    unsigned T = sh_T;
    for (int i = t; i < NN; i += 1024) {
        unsigned b = __float_as_uint(sc[i]);
        if (b >= T) {
            int a = i / KK;
            int p = i - a*KK;
            unsigned id = (unsigned)(p*3 + a);
            int pos = atomicAdd(&g_cand_count, 1);
            if (pos < CAP)
                g_cand[pos] = ((u64)b << 32) | (u64)(0xFFFFFFFFu - id);
        }
    }
}

// Partial all-pairs rank: block (bi, q) ranks candidates [bi*256, bi*256+256)
// against j-quarter q of [0, cnt). Partial counts accumulate via atomicAdd
// into g_rank (zeroed by scan_k). Spreads the ALU work over ~4x more SMs.
__global__ void __launch_bounds__(256) rank_part_k() {
    __shared__ u64 tile[256];
    int cnt = g_cand_count; if (cnt > CAP) cnt = CAP;
    int bi = blockIdx.x, q = blockIdx.y;
    if (bi*256 >= cnt) return;
    int i = bi*256 + threadIdx.x;
    u64 my = (i < cnt) ? g_cand[i] : 0xFFFFFFFFFFFFFFFFull;
    int qs = (q * cnt) >> 2;
    int qe = ((q + 1) * cnt) >> 2;
    int rank = 0;
    for (int base = qs; base < qe; base += 256) {
        int j = base + threadIdx.x;
        tile[threadIdx.x] = (j < qe) ? g_cand[j] : 0ull;   // 0 never counts
        __syncthreads();
        #pragma unroll 8
        for (int k = 0; k < 256; ++k) rank += (tile[k] > my) ? 1 : 0;
        __syncthreads();
    }
    if (i < cnt && rank > 0) atomicAdd(&g_rank[i], rank);
}

// Box transform + scatter by exact rank (rank < PRE -> sorted top-PRE slot).
__global__ void __launch_bounds__(256) transform_k(const float* __restrict__ deltas,
                                                   const float* __restrict__ ii,
                                                   const float* __restrict__ anc) {
    int cnt = g_cand_count; if (cnt > CAP) cnt = CAP;
    int i = blockIdx.x*256 + threadIdx.x;
    if (i >= cnt) return;
    int r = g_rank[i];
    if (r >= PRE) return;
    u64 my = g_cand[i];

    int idx = (int)(0xFFFFFFFFu - (unsigned)(my & 0xFFFFFFFFull));
    float score = __uint_as_float((unsigned)(my >> 32));
    int a = idx % 3;
    int p = idx / 3;
    int w = p % WW;
    int h = (p / WW) % HH;
    int s = p / (WW*HH);
    float shx = 4.0f * (float)w, shy = 4.0f * (float)h, shz = 4.0f * (float)s;
    float x1a = __fadd_rn(shx, anc[a*6+0]);
    float y1a = __fadd_rn(shy, anc[a*6+1]);
    float z1a = __fadd_rn(shz, anc[a*6+2]);
    float x2a = __fadd_rn(shx, anc[a*6+3]);
    float y2a = __fadd_rn(shy, anc[a*6+4]);
    float z2a = __fadd_rn(shz, anc[a*6+5]);
    float ww_ = __fadd_rn(__fsub_rn(x2a, x1a), 1.0f);
    float hh_ = __fadd_rn(__fsub_rn(y2a, y1a), 1.0f);
    float dd_ = __fadd_rn(__fsub_rn(z2a, z1a), 1.0f);
    float cx = __fadd_rn(x1a, __fmul_rn(0.5f, ww_));
    float cy = __fadd_rn(y1a, __fmul_rn(0.5f, hh_));
    float cz = __fadd_rn(z1a, __fmul_rn(0.5f, dd_));
    const float* dp = deltas + p;
    float dx = dp[(6*a+0)*KK];
    float dy = dp[(6*a+1)*KK];
    float dz = dp[(6*a+2)*KK];
    float dw = dp[(6*a+3)*KK];
    float dh = dp[(6*a+4)*KK];
    float dd = dp[(6*a+5)*KK];
    float pcx = __fadd_rn(__fmul_rn(dx, ww_), cx);
    float pcy = __fadd_rn(__fmul_rn(dy, hh_), cy);
    float pcz = __fadd_rn(__fmul_rn(dz, dd_), cz);
    float pw = __fmul_rn(expf(dw), ww_);
    float ph = __fmul_rn(expf(dh), hh_);
    float pd = __fmul_rn(expf(dd), dd_);
    float slices = ii[0], height = ii[1], width = ii[2], scale = ii[3];
    float wx = __fsub_rn(width, 1.0f);
    float hy = __fsub_rn(height, 1.0f);
    float sz = __fsub_rn(slices, 1.0f);
    float x1 = fminf(fmaxf(__fsub_rn(pcx, __fmul_rn(0.5f, pw)), 0.0f), wx);
    float y1 = fminf(fmaxf(__fsub_rn(pcy, __fmul_rn(0.5f, ph)), 0.0f), hy);
    float z1 = fminf(fmaxf(__fsub_rn(pcz, __fmul_rn(0.5f, pd)), 0.0f), sz);
    float x2 = fminf(fmaxf(__fsub_rn(__fadd_rn(pcx, __fmul_rn(0.5f, pw)), 1.0f), 0.0f), wx);
    float y2 = fminf(fmaxf(__fsub_rn(__fadd_rn(pcy, __fmul_rn(0.5f, ph)), 1.0f), 0.0f), hy);
    float z2 = fminf(fmaxf(__fsub_rn(__fadd_rn(pcz, __fmul_rn(0.5f, pd)), 1.0f), 0.0f), sz);
    float ss_ = __fadd_rn(__fsub_rn(x2, x1), 1.0f);
    float xc = __fadd_rn(x1, __fmul_rn(ss_, 0.5f));
    float yc = __fadd_rn(y1, __fmul_rn(ss_, 0.5f));
    float zc = __fadd_rn(z1, __fmul_rn(ss_, 0.5f));
    float minsz = __fmul_rn(8.0f, scale);
    int valid = (ss_ >= minsz) && (xc < width) && (yc < height) && (zc < slices);
    float vy = __fadd_rn(__fsub_rn(y2, y1), 1.0f);
    float vz = __fadd_rn(__fsub_rn(z2, z1), 1.0f);
    float vol = __fmul_rn(__fmul_rn(ss_, vy), vz);
    g_bx1[r] = x1; g_by1[r] = y1; g_bz1[r] = z1;
    g_bx2[r] = x2; g_by2[r] = y2; g_bz2[r] = z2;
    g_volv[r] = vol;
    g_valid[r] = valid;
    g_order[r] = idx;
    g_score[r] = score;
}

// IoU mask, tiled (128 rows x 32 cols): thread = one row, columns in smem.
__global__ void __launch_bounds__(128) mask_k() {
    __shared__ float cx1[32], cy1[32], cz1[32], cx2[32], cy2[32], cz2[32], cv[32];
    int chunk = blockIdx.x;             // col chunk: cols [32*chunk, 32*chunk+32)
    int rb    = blockIdx.y;             // rowblock of 128
    int t = threadIdx.x;
    int r = rb*128 + t;
    unsigned* m32 = (unsigned*)g_mask;
    if (rb*128 >= chunk*32 + 32) {      // whole block in lower triangle
        if (r < PRE) m32[r*64 + chunk] = 0u;
        return;
    }
    if (t < 32) {
        int c = chunk*32 + t;
        if (c < PRE) {
            cx1[t] = g_bx1[c]; cy1[t] = g_by1[c]; cz1[t] = g_bz1[c];
            cx2[t] = g_bx2[c]; cy2[t] = g_by2[c]; cz2[t] = g_bz2[c];
            cv[t]  = g_volv[c];
        }
    }
    __syncthreads();
    if (r >= PRE) return;
    float x1 = g_bx1[r], y1 = g_by1[r], z1 = g_bz1[r];
    float x2 = g_bx2[r], y2 = g_by2[r], z2 = g_bz2[r];
    float vr = g_volv[r];
    unsigned bits = 0u;
    #pragma unroll 8
    for (int k = 0; k < 32; ++k) {
        int j = chunk*32 + k;
        if (j < PRE && j > r) {
            float iw = fmaxf(__fadd_rn(__fsub_rn(fminf(x2, cx2[k]), fmaxf(x1, cx1[k])), 1.0f), 0.0f);
            float ih = fmaxf(__fadd_rn(__fsub_rn(fminf(y2, cy2[k]), fmaxf(y1, cy1[k])), 1.0f), 0.0f);
            float id = fmaxf(__fadd_rn(__fsub_rn(fminf(z2, cz2[k]), fmaxf(z1, cz1[k])), 1.0f), 0.0f);
            float inter = __fmul_rn(__fmul_rn(iw, ih), id);
            if (inter > 0.0f) {
                float denom = __fsub_rn(__fadd_rn(vr, cv[k]), inter);
                float iou = __fdiv_rn(inter, denom);
                if (iou > NMS_T) bits |= (1u << k);
            }
        }
    }
    m32[r*64 + chunk] = bits;
}

__device__ __forceinline__ void fill_one(float* out, int i, int pos) {
    int base = pos*7;
    out[base+0] = 0.0f;
    out[base+1] = g_bx1[i];
    out[base+2] = g_by1[i];
    out[base+3] = g_bz1[i];
    out[base+4] = g_bx2[i];
    out[base+5] = g_by2[i];
    out[base+6] = g_bz2[i];
    out[POST*7 + pos] = g_score[i];          // 2100..2399
    out[POST*8 + pos] = (float)g_order[i];   // 2400..2699
    out[POST*9 + pos] = 1.0f;                // 2700..2999
}

// One NMS chunk step: prefetch rows (c+2)*16.. into NXT, decide chunk c from
// CUR (16-bit window on the owning lane), broadcast, OR-tree apply.
#define NMS_STEP(CUR, NXT, C) do {                                          \
    int nbase_ = ((C) + 2) * 16;                                            \
    _Pragma("unroll")                                                       \
    for (int b_ = 0; b_ < 16; ++b_) {                                       \
        int row_ = nbase_ + b_;                                             \
        NXT[b_] = (row_ < PRE) ? g_mask[(size_t)row_*WORDS + lane] : 0ull;  \
    }                                                                       \
    int w_  = ((C) * 16) >> 6;                                              \
    int sh_ = ((C) * 16) & 63;                                              \
    unsigned acc_ = 0u;                                                     \
    if (lane == w_) {                                                       \
        unsigned w16_ = (unsigned)(rm >> sh_) & 0xFFFFu;                    \
        _Pragma("unroll")                                                   \
        for (int b_ = 0; b_ < 16; ++b_) {                                   \
            unsigned vw_ = (unsigned)(CUR[b_] >> sh_) & 0xFFFFu;            \
            unsigned sup_ = (w16_ >> b_) & 1u;                              \
            acc_ |= (sup_ ^ 1u) << b_;                                      \
            w16_ |= sup_ ? 0u : vw_;                                        \
        }                                                                   \
    }                                                                       \
    acc_ = __shfl_sync(0xffffffffu, acc_, w_);                              \
    u64 a0_ = (((acc_>>0)&1u)?CUR[0]:0ull)  | (((acc_>>1)&1u)?CUR[1]:0ull)  \
            | (((acc_>>2)&1u)?CUR[2]:0ull)  | (((acc_>>3)&1u)?CUR[3]:0ull); \
    u64 a1_ = (((acc_>>4)&1u)?CUR[4]:0ull)  | (((acc_>>5)&1u)?CUR[5]:0ull)  \
            | (((acc_>>6)&1u)?CUR[6]:0ull)  | (((acc_>>7)&1u)?CUR[7]:0ull); \
    u64 a2_ = (((acc_>>8)&1u)?CUR[8]:0ull)  | (((acc_>>9)&1u)?CUR[9]:0ull)  \
            | (((acc_>>10)&1u)?CUR[10]:0ull)| (((acc_>>11)&1u)?CUR[11]:0ull);\
    u64 a3_ = (((acc_>>12)&1u)?CUR[12]:0ull)| (((acc_>>13)&1u)?CUR[13]:0ull)\
            | (((acc_>>14)&1u)?CUR[14]:0ull)| (((acc_>>15)&1u)?CUR[15]:0ull);\
    rm |= (a0_|a1_) | (a2_|a3_);                                            \
} while (0)

// Merged NMS-reduce + output, 256 threads. Warp 0: serial greedy reduce with
// 2-deep (triple-buffered) register prefetch so the L2 latency is fully hidden
// behind two chunk periods. Warps 1..7 init the output buffer concurrently.
__global__ void __launch_bounds__(256) final_k(float* __restrict__ out, int out_size) {
    __shared__ int sc[256];
    __shared__ u64 rw[WORDS];
    int t = threadIdx.x;

    if (t < 32) {
        int lane = t;
        u64 rm = 0ull;
        #pragma unroll
        for (int b = 0; b < 64; ++b) {
            int j = lane*64 + b;
            int inval = (j < PRE) ? (g_valid[j] ? 0 : 1) : 1;
            rm |= ((u64)inval) << b;
        }
        // NCH = 125 chunks of 16 candidates
        u64 buf0[16], buf1[16], buf2[16];
        #pragma unroll
        for (int b = 0; b < 16; ++b) buf0[b] = g_mask[(size_t)b*WORDS + lane];
        #pragma unroll
        for (int b = 0; b < 16; ++b) buf1[b] = g_mask[(size_t)(16+b)*WORDS + lane];
        for (int c = 0; c < 123; c += 3) {
            NMS_STEP(buf0, buf2, c);
            NMS_STEP(buf1, buf0, c+1);
            NMS_STEP(buf2, buf1, c+2);
        }
        NMS_STEP(buf0, buf2, 123);
        NMS_STEP(buf1, buf0, 124);
        rw[lane] = rm;
    } else {
        for (int o = t - 32; o < POST*8; o += 224) if (o < out_size) out[o] = 0.0f;
        for (int o = t - 32; o < POST; o += 224) {
            if (POST*8 + o < out_size) out[POST*8 + o] = -1.0f;
            if (POST*9 + o < out_size) out[POST*9 + o] = 0.0f;
        }
    }
    __syncthreads();

    int kk[8];
    int ksum = 0;
    #pragma unroll
    for (int c = 0; c < 8; ++c) {
        int i = 8*t + c;
        int k = 0;
        if (i < PRE) k = (g_valid[i] && !((rw[i>>6] >> (i & 63)) & 1ull)) ? 1 : 0;
        kk[c] = k;
        ksum += k;
    }
    sc[t] = ksum;
    __syncthreads();
    for (int off = 1; off < 256; off <<= 1) {
        int v = (t >= off) ? sc[t-off] : 0;
        __syncthreads();
        sc[t] += v;
        __syncthreads();
    }
    int pos = sc[t] - ksum;
    if (out_size >= POST*10) {
        #pragma unroll
        for (int c = 0; c < 8; ++c) {
            if (kk[c] && pos < POST) fill_one(out, 8*t + c, pos);
            pos += kk[c];
        }
    }
    if (t == 0) g_cand_count = 0;   // clean state for next graph replay
}

// ---------------- launch ----------------
extern "C" void kernel_launch(void* const* d_in, const int* in_sizes, int n_in,
                              void* d_out, int out_size) {
    const float* scores  = (const float*)d_in[0];
    const float* deltas  = (const float*)d_in[1];
    const float* iminfo  = (const float*)d_in[2];
    const float* anchors = (const float*)d_in[3];
    float* out = (float*)d_out;

    scan_k<<<768, 512>>>((const float4*)scores);       // NN/4 threads exactly
    fb_all_k<<<1, 1024>>>(scores);                     // early-exits normally
    rank_part_k<<<dim3(CAP/256, 4), 256>>>();
    transform_k<<<CAP/256, 256>>>(deltas, iminfo, anchors);
    mask_k<<<dim3(64, (PRE + 127)/128), 128>>>();
    final_k<<<1, 256>>>(out, out_size);
}